// round 1
// baseline (speedup 1.0000x reference)
#include <cuda_runtime.h>
#include <math_constants.h>

// Problem constants (fixed by setup_inputs)
#define SLEN 4096
#define HDIM 1024
#define BATCH 8
#define KSEL 8

#define TILE_S 64
#define TILE_R 32
#define NTILES (SLEN / TILE_S)
#define A_ROW 36                      // 32 h + pad: bank = 4s+lane -> conflict-free reads
#define G_ROW 65                      // 64 s + pad: bank = lane+s -> conflict-free reads
#define A_BUF (TILE_S * A_ROW)        // 2304 floats
#define G_BUF (TILE_R * G_ROW)        // 2080 floats
#define SMEM_FLOATS (2 * A_BUF + 2 * G_BUF)   // 8768 floats = 35072 B (< 48KB static)

__device__ float g_pooled[BATCH * HDIM];

static __device__ __forceinline__ unsigned smem_u32(const void* p) {
    return (unsigned)__cvta_generic_to_shared(p);
}
static __device__ __forceinline__ void cp_async4(unsigned dst, const void* src) {
    asm volatile("cp.async.ca.shared.global [%0], [%1], 4;" :: "r"(dst), "l"(src) : "memory");
}
static __device__ __forceinline__ void cp_async16(unsigned dst, const void* src) {
    asm volatile("cp.async.cg.shared.global [%0], [%1], 16;" :: "r"(dst), "l"(src) : "memory");
}
static __device__ __forceinline__ void cp_commit() {
    asm volatile("cp.async.commit_group;" ::: "memory");
}
template <int N> static __device__ __forceinline__ void cp_wait() {
    asm volatile("cp.async.wait_group %0;" :: "n"(N) : "memory");
}

// Insert (sc, tv) into ascending sorted top-8 arrays. Precondition: sc > s8[0].
static __device__ __forceinline__ void insert8(float sc, float tv, float (&s8)[8], float (&t8)[8]) {
    bool placed = false;
#pragma unroll
    for (int j = 0; j < 7; ++j) {
        if (!placed) {
            if (sc > s8[j + 1]) { s8[j] = s8[j + 1]; t8[j] = t8[j + 1]; }
            else { s8[j] = sc; t8[j] = tv; placed = true; }
        }
    }
    if (!placed) { s8[7] = sc; t8[7] = tv; }
}

__global__ __launch_bounds__(256, 1)
void topk_pool_kernel(const float* __restrict__ hidden, const float* __restrict__ gumbel) {
    __shared__ float sm[SMEM_FLOATS];
    float* As = sm;                 // [2][TILE_S][A_ROW]
    float* Gs = sm + 2 * A_BUF;     // [2][TILE_R][G_ROW]

    const int t = threadIdx.x;
    const int blk = blockIdx.x;
    const int b = blk >> 5;                    // 0..7
    const int h0 = (blk & 31) << 5;            // 0..992
    const float* hbase = hidden + (size_t)b * SLEN * HDIM + h0;
    const float* gbase = gumbel + (size_t)(b * HDIM + h0) * SLEN;

    const int lane = t & 31;   // row within tile (h index)
    const int sub = t >> 5;    // 0..7: s-subrange within tile

    auto issue = [&](int tile, int buf) {
        // hidden tile: TILE_S x 32 floats, 16B cp.async, coalesced (128B/warp)
        const int u = t & 7;
        const int si0 = t >> 3;     // 0..31
        unsigned abuf = smem_u32(&As[buf * A_BUF]);
#pragma unroll
        for (int k = 0; k < 2; ++k) {
            int si = si0 + 32 * k;
            cp_async16(abuf + (unsigned)(si * A_ROW + 4 * u) * 4u,
                       hbase + (size_t)(tile * TILE_S + si) * HDIM + 4 * u);
        }
        // gumbel tile: 32 rows x TILE_S floats, 4B cp.async, coalesced (128B/warp)
        unsigned gb = smem_u32(&Gs[buf * G_BUF]);
#pragma unroll
        for (int k = 0; k < 8; ++k) {
            int idx = t + 256 * k;
            int row = idx >> 6;       // 0..31
            int sj = idx & 63;
            cp_async4(gb + (unsigned)(row * G_ROW + sj) * 4u,
                      gbase + (size_t)row * SLEN + tile * TILE_S + sj);
        }
        cp_commit();
    };

    float s8[8], t8[8];
#pragma unroll
    for (int j = 0; j < 8; ++j) { s8[j] = -CUDART_INF_F; t8[j] = 0.f; }

    issue(0, 0);
    issue(1, 1);

    for (int tile = 0; tile < NTILES; ++tile) {
        if (tile < NTILES - 1) cp_wait<1>(); else cp_wait<0>();
        __syncthreads();

        const int buf = tile & 1;
        const float* Ab = &As[buf * A_BUF];
        const float* Gb = &Gs[buf * G_BUF + lane * G_ROW];

#pragma unroll
        for (int i = 0; i < TILE_S / 8; ++i) {
            int s = sub * (TILE_S / 8) + i;
            float tv = fmaxf(Ab[s * A_ROW + lane], 0.f);   // relu
            float g = Gb[s];
            if (tv > 0.f) {
                float sc = __logf(tv) + g;
                if (sc > s8[0]) insert8(sc, tv, s8, t8);
            }
        }
        __syncthreads();
        if (tile + 2 < NTILES) issue(tile + 2, buf);
    }

    // Merge 8 per-thread lists per row. Reuse smem (all tile reads are done).
    float* M = sm;  // [32 rows][64 candidates][2]
    {
        int base = (lane * 64 + sub * 8) * 2;
#pragma unroll
        for (int j = 0; j < 8; ++j) {
            M[base + 2 * j] = s8[j];
            M[base + 2 * j + 1] = t8[j];
        }
    }
    __syncthreads();

    if (t < TILE_R) {
        float fs[8], ft[8];
#pragma unroll
        for (int j = 0; j < 8; ++j) { fs[j] = -CUDART_INF_F; ft[j] = 0.f; }
        for (int c = 0; c < 64; ++c) {
            float sc = M[(t * 64 + c) * 2];
            float tv = M[(t * 64 + c) * 2 + 1];
            if (sc > fs[0]) insert8(sc, tv, fs, ft);
        }
        float sum = 0.f;
#pragma unroll
        for (int j = 0; j < 8; ++j) sum += ft[j];
        g_pooled[b * HDIM + h0 + t] = sum;
    }
}

// out[i][j] = tanh(b[j] + sum_h pooled[i][h] * W[j][h]);  one warp per output column j.
__global__ __launch_bounds__(256, 1)
void gemm_tanh_kernel(const float* __restrict__ W, const float* __restrict__ bias,
                      float* __restrict__ out) {
    const int warp = threadIdx.x >> 5;
    const int lane = threadIdx.x & 31;
    const int j = blockIdx.x * 8 + warp;   // 0..1023

    const float* wrow = W + (size_t)j * HDIM;
    float acc[BATCH];
#pragma unroll
    for (int i = 0; i < BATCH; ++i) acc[i] = 0.f;

    for (int h = lane; h < HDIM; h += 32) {
        float w = wrow[h];
#pragma unroll
        for (int i = 0; i < BATCH; ++i)
            acc[i] = fmaf(g_pooled[i * HDIM + h], w, acc[i]);
    }
#pragma unroll
    for (int i = 0; i < BATCH; ++i) {
#pragma unroll
        for (int off = 16; off > 0; off >>= 1)
            acc[i] += __shfl_xor_sync(0xffffffffu, acc[i], off);
    }
    if (lane == 0) {
        float bj = bias[j];
#pragma unroll
        for (int i = 0; i < BATCH; ++i)
            out[i * HDIM + j] = tanhf(acc[i] + bj);
    }
}

extern "C" void kernel_launch(void* const* d_in, const int* in_sizes, int n_in,
                              void* d_out, int out_size) {
    const float* hidden = (const float*)d_in[0];   // [8, 4096, 1024]
    const float* gumbel = (const float*)d_in[1];   // [8192, 4096]
    const float* W = (const float*)d_in[2];        // [1024, 1024]
    const float* bias = (const float*)d_in[3];     // [1024]
    // d_in[4] = sample (always 8) — compile-time constant KSEL
    float* out = (float*)d_out;                    // [8, 1024] float32

    topk_pool_kernel<<<BATCH * (HDIM / TILE_R), 256>>>(hidden, gumbel);
    gemm_tanh_kernel<<<HDIM / 8, 256>>>(W, bias, out);
}

// round 2
// speedup vs baseline: 1.0141x; 1.0141x over previous
#include <cuda_runtime.h>
#include <math_constants.h>

// Problem constants (fixed by setup_inputs)
#define SLEN 4096
#define HDIM 1024
#define BATCH 8
#define KSEL 8

#define TILE_S 64
#define TILE_R 32
#define NTILES (SLEN / TILE_S)       // 64
#define STAGES 5
#define A_ROW 36                     // 32 h + pad: bank = (4s+lane)%32 -> conflict-free
#define G_ROW 65                     // 64 s + pad: bank = (lane+s)%32 -> conflict-free
#define A_BUF (TILE_S * A_ROW)       // 2304 floats (9216 B)
#define G_BUF (TILE_R * G_ROW)       // 2080 floats (8320 B)
#define STG   (A_BUF + G_BUF)        // 4384 floats / stage
#define SMEM_BYTES (STAGES * STG * 4)  // 87,680 B (dynamic)

__device__ __align__(16) float g_pooled[BATCH * HDIM];

static __device__ __forceinline__ unsigned smem_u32(const void* p) {
    return (unsigned)__cvta_generic_to_shared(p);
}
static __device__ __forceinline__ void cp_async4(unsigned dst, const void* src) {
    asm volatile("cp.async.ca.shared.global [%0], [%1], 4;" :: "r"(dst), "l"(src) : "memory");
}
static __device__ __forceinline__ void cp_async16(unsigned dst, const void* src) {
    asm volatile("cp.async.cg.shared.global [%0], [%1], 16;" :: "r"(dst), "l"(src) : "memory");
}
static __device__ __forceinline__ void cp_commit() {
    asm volatile("cp.async.commit_group;" ::: "memory");
}
template <int N> static __device__ __forceinline__ void cp_wait() {
    asm volatile("cp.async.wait_group %0;" :: "n"(N) : "memory");
}

// Insert (sc, tv) into ascending sorted top-8 arrays. Precondition: sc > s8[0].
static __device__ __forceinline__ void insert8(float sc, float tv, float (&s8)[8], float (&t8)[8]) {
    bool placed = false;
#pragma unroll
    for (int j = 0; j < 7; ++j) {
        if (!placed) {
            if (sc > s8[j + 1]) { s8[j] = s8[j + 1]; t8[j] = t8[j + 1]; }
            else { s8[j] = sc; t8[j] = tv; placed = true; }
        }
    }
    if (!placed) { s8[7] = sc; t8[7] = tv; }
}

__global__ __launch_bounds__(256, 2)
void topk_pool_kernel(const float* __restrict__ hidden, const float* __restrict__ gumbel) {
    extern __shared__ float sm[];   // STAGES x [A_BUF | G_BUF]

    const int t = threadIdx.x;
    const int blk = blockIdx.x;
    const int b = blk >> 5;                    // 0..7
    const int h0 = (blk & 31) << 5;            // 0..992
    const float* hbase = hidden + (size_t)b * SLEN * HDIM + h0;
    const float* gbase = gumbel + (size_t)(b * HDIM + h0) * SLEN;

    const int lane = t & 31;   // row within tile (h index)
    const int sub = t >> 5;    // 0..7: s-subrange within tile

    // hidden load mapping: lanes 0-7 cover one 128B row segment
    const int u = t & 7;
    const int si0 = t >> 3;    // 0..31
    const unsigned aoff0 = (unsigned)(si0 * A_ROW + 4 * u) * 4u;
    const unsigned aoff1 = (unsigned)((si0 + 32) * A_ROW + 4 * u) * 4u;

    auto issue = [&](int tile, int buf) {
        unsigned sbase = smem_u32(sm + buf * STG);
        const float* hsrc = hbase + (size_t)tile * TILE_S * HDIM;
        cp_async16(sbase + aoff0, hsrc + (size_t)si0 * HDIM + 4 * u);
        cp_async16(sbase + aoff1, hsrc + (size_t)(si0 + 32) * HDIM + 4 * u);
        unsigned gb = sbase + (unsigned)A_BUF * 4u;
        const float* gsrc = gbase + tile * TILE_S;
#pragma unroll
        for (int k = 0; k < 8; ++k) {
            int idx = t + 256 * k;
            int row = idx >> 6;       // 0..31
            int sj = idx & 63;
            cp_async4(gb + (unsigned)(row * G_ROW + sj) * 4u,
                      gsrc + (size_t)row * SLEN + sj);
        }
        cp_commit();
    };

    float s8[8], t8[8];
#pragma unroll
    for (int j = 0; j < 8; ++j) { s8[j] = -CUDART_INF_F; t8[j] = 0.f; }

    // Prologue: fill STAGES-1 = 4 stages.
#pragma unroll
    for (int p = 0; p < STAGES - 1; ++p) issue(p, p);

    int cbuf = 0;               // compute buffer
    int ibuf = STAGES - 1;      // next issue buffer

    for (int tile = 0; tile < NTILES; ++tile) {
        if (tile < NTILES - (STAGES - 2)) cp_wait<STAGES - 2>();
        else cp_wait<0>();
        // Single barrier: (a) makes everyone's cp.async for this tile visible,
        // (b) proves all threads finished computing tile-1, so issuing into
        // buffer (tile-1)%STAGES below is safe.
        __syncthreads();

        const float* Ab = sm + cbuf * STG;
        const float* Gb = Ab + A_BUF + lane * G_ROW + sub * 8;

#pragma unroll
        for (int i = 0; i < 8; ++i) {
            int s = sub * 8 + i;
            float tv = fmaxf(Ab[s * A_ROW + lane], 0.f);   // relu
            if (tv > 0.f) {
                float sc = __logf(tv) + Gb[i];
                if (sc > s8[0]) insert8(sc, tv, s8, t8);
            }
        }

        if (tile + STAGES - 1 < NTILES) {
            issue(tile + STAGES - 1, ibuf);
            if (++ibuf == STAGES) ibuf = 0;
        }
        if (++cbuf == STAGES) cbuf = 0;
    }

    // Merge 8 per-thread lists per row through smem (reuse stage memory).
    __syncthreads();
    float* M = sm;  // [32 rows][64 candidates][2] = 16 KB
    {
        int base = (lane * 64 + sub * 8) * 2;
#pragma unroll
        for (int j = 0; j < 8; ++j) {
            M[base + 2 * j] = s8[j];
            M[base + 2 * j + 1] = t8[j];
        }
    }
    __syncthreads();

    if (t < TILE_R) {
        float fs[8], ft[8];
#pragma unroll
        for (int j = 0; j < 8; ++j) { fs[j] = -CUDART_INF_F; ft[j] = 0.f; }
        for (int c = 0; c < 64; ++c) {
            float sc = M[(t * 64 + c) * 2];
            float tv = M[(t * 64 + c) * 2 + 1];
            if (sc > fs[0]) insert8(sc, tv, fs, ft);
        }
        float sum = 0.f;
#pragma unroll
        for (int j = 0; j < 8; ++j) sum += ft[j];
        g_pooled[b * HDIM + h0 + t] = sum;
    }
}

// GEMM v2: out[i][j] = tanh(b[j] + sum_h pooled[i][h] * W[j][h])
// Block = 256 threads = 8 warps: 4 columns x 2 half-H warps. pooled staged in smem.
__global__ __launch_bounds__(256, 2)
void gemm_tanh_kernel(const float* __restrict__ W, const float* __restrict__ bias,
                      float* __restrict__ out) {
    __shared__ float sp[BATCH * HDIM];      // 32 KB
    __shared__ float red[4][2][BATCH];

    // Cooperative load of pooled (float4, coalesced; hits L2 — just written).
    {
        const float4* src = (const float4*)g_pooled;
        float4* dst = (float4*)sp;
#pragma unroll
        for (int k = 0; k < (BATCH * HDIM / 4) / 256; ++k)
            dst[threadIdx.x + 256 * k] = src[threadIdx.x + 256 * k];
    }
    __syncthreads();

    const int w = threadIdx.x >> 5;
    const int lane = threadIdx.x & 31;
    const int jj = w >> 1;                 // 0..3 column within block
    const int half = w & 1;                // 0..1 half of H
    const int j = blockIdx.x * 4 + jj;

    const float* wrow = W + (size_t)j * HDIM + half * 512;
    float acc[BATCH];
#pragma unroll
    for (int i = 0; i < BATCH; ++i) acc[i] = 0.f;

#pragma unroll
    for (int c = 0; c < 16; ++c) {
        int h = c * 32 + lane;             // coalesced 128B per c; bank = lane
        float wv = wrow[h];
        const float* p = sp + half * 512 + h;
#pragma unroll
        for (int i = 0; i < BATCH; ++i)
            acc[i] = fmaf(p[i * HDIM], wv, acc[i]);
    }
#pragma unroll
    for (int i = 0; i < BATCH; ++i) {
#pragma unroll
        for (int off = 16; off > 0; off >>= 1)
            acc[i] += __shfl_xor_sync(0xffffffffu, acc[i], off);
    }
    if (lane == 0) {
#pragma unroll
        for (int i = 0; i < BATCH; ++i) red[jj][half][i] = acc[i];
    }
    __syncthreads();

    if (threadIdx.x < 32) {
        int i = threadIdx.x & 7;           // batch
        int jj2 = threadIdx.x >> 3;        // 0..3
        int jo = blockIdx.x * 4 + jj2;
        float v = red[jj2][0][i] + red[jj2][1][i] + bias[jo];
        out[i * HDIM + jo] = tanhf(v);
    }
}

extern "C" void kernel_launch(void* const* d_in, const int* in_sizes, int n_in,
                              void* d_out, int out_size) {
    const float* hidden = (const float*)d_in[0];   // [8, 4096, 1024]
    const float* gumbel = (const float*)d_in[1];   // [8192, 4096]
    const float* W = (const float*)d_in[2];        // [1024, 1024]
    const float* bias = (const float*)d_in[3];     // [1024]
    float* out = (float*)d_out;                    // [8, 1024] float32

    static bool attr_set = false;
    if (!attr_set) {
        cudaFuncSetAttribute(topk_pool_kernel,
                             cudaFuncAttributeMaxDynamicSharedMemorySize, SMEM_BYTES);
        attr_set = true;
    }

    topk_pool_kernel<<<BATCH * (HDIM / TILE_R), 256, SMEM_BYTES>>>(hidden, gumbel);
    gemm_tanh_kernel<<<HDIM / 4, 256>>>(W, bias, (float*)d_out);
}